// round 9
// baseline (speedup 1.0000x reference)
#include <cuda_runtime.h>
#include <cstdint>
#include <stdint.h>

#define B_SZ   256
#define T_SZ   2048
#define N_SZ   128
#define NPAIRS (B_SZ * T_SZ)   // 524288

// Solve workspace: 128 rows x 132 floats (cols 0..127 = I+A, 128/129 = RHS)
#define WROW   132
#define WROW4  33
#define BSROW  129

// Scratch (device globals — no allocation allowed)
__device__ __align__(16) float g_h[NPAIRS * 2];   // hidden, [t][b] float2 layout
__device__ __align__(16) float g_q0[N_SZ];        // Q[:,0]
__device__ __align__(16) float g_q1[N_SZ];        // Q[:,1]

__device__ __forceinline__ float fast_rcp(float x) {
    float r;
    asm("rcp.approx.f32 %0, %1;" : "=f"(r) : "f"(x));
    return r;
}

__device__ __forceinline__ float getc(float4 v, int m) {
    return m == 0 ? v.x : (m == 1 ? v.y : (m == 2 ? v.z : v.w));
}

// ---------------------------------------------------------------------------
// Phase 1 (256 threads/block):
//   block 0:     Cayley solve — PANEL-4 BLOCKED Gaussian elimination
//   blocks 1..2: leaky RNN — threads 0..127 each run one sequence,
//                streaming their contiguous 24KB of u via __ldg rotation
// ---------------------------------------------------------------------------
__global__ void __launch_bounds__(256) phase1_kernel(
        const float* __restrict__ u,
        const float* __restrict__ matB,
        const float* __restrict__ wIn,
        const float* __restrict__ wRec) {
    extern __shared__ float smem[];
    const int tid = threadIdx.x;

    if (blockIdx.x == 0) {
        // ================= Cayley solve: blocked GE =================
        float*  Wf    = smem;                       // [128][132]
        float4* W4    = (float4*)smem;              // row i, group g: i*33+g
        float*  Bs    = smem + N_SZ * WROW;         // [128][129]
        float*  prowf = Bs + N_SZ * BSROW;          // [4][132] corrected pivot rows
        float4* prow4 = (float4*)prowf;             // [4][33]
        float*  fb    = prowf + 4 * WROW;           // [4][128] elimination factors
        __shared__ float z0s[N_SZ], z1s[N_SZ];
        const int i = tid;                          // row (threads 0..127)

        // ---- stage matB into smem, coalesced float4 loads ----
        for (int idx = tid; idx < N_SZ * 32; idx += 256) {
            int r = idx >> 5, c4 = idx & 31;
            float4 v = ((const float4*)matB)[r * 32 + c4];
            float* dst = Bs + r * BSROW + c4 * 4;
            dst[0] = v.x; dst[1] = v.y; dst[2] = v.z; dst[3] = v.w;
        }
        __syncthreads();

        // ---- build augmented [I+A | e0 e1] ----
        if (i < N_SZ) {
            float* wr = Wf + i * WROW;
            #pragma unroll 4
            for (int j = 0; j < N_SZ; j++) {
                float a = Bs[i * BSROW + j] - Bs[j * BSROW + i];
                wr[j] = (i == j ? 1.0f : 0.0f) + a;
            }
            wr[128] = (i == 0) ? 1.0f : 0.0f;
            wr[129] = (i == 1) ? 1.0f : 0.0f;
            wr[130] = 0.0f; wr[131] = 0.0f;
        }
        __syncthreads();

        // ---- blocked forward elimination: 32 panels of 4 pivots ----
        for (int p = 0; p < 32; p++) {
            // each row's panel column-slice, kept in a register
            float4 cp = make_float4(0.f, 0.f, 0.f, 0.f);
            if (i < N_SZ) cp = W4[i * WROW4 + p];

            #pragma unroll
            for (int m = 0; m < 4; m++) {
                const int k = 4 * p + m;

                // step 1: corrected pivot row k -> prow[m]  (33 threads)
                if (tid < WROW4) {
                    float4 v = W4[k * WROW4 + tid];
                    #pragma unroll
                    for (int j = 0; j < 4; j++) {
                        if (j < m) {
                            float fj = fb[j * N_SZ + k];       // broadcast
                            float4 pr = prow4[j * WROW4 + tid];
                            v.x = fmaf(-fj, pr.x, v.x);
                            v.y = fmaf(-fj, pr.y, v.y);
                            v.z = fmaf(-fj, pr.z, v.z);
                            v.w = fmaf(-fj, pr.w, v.w);
                        }
                    }
                    prow4[m * WROW4 + tid] = v;
                }
                __syncthreads();

                // step 2: factors f_m for all rows + register cp correction
                if (i < N_SZ) {
                    float piv  = prowf[m * WROW + k];          // broadcast
                    float rinv = fast_rcp(piv);
                    float f = (i > k) ? getc(cp, m) * rinv : 0.0f;
                    fb[m * N_SZ + i] = f;
                    float4 pp = prow4[m * WROW4 + p];          // pivot's panel slice
                    if (m < 1) cp.y = fmaf(-f, pp.y, cp.y);
                    if (m < 2) cp.z = fmaf(-f, pp.z, cp.z);
                    if (m < 3) cp.w = fmaf(-f, pp.w, cp.w);
                }
                __syncthreads();
            }

            // panel end: rank-4 update of rows below panel (one touch per row)
            if (i < N_SZ && i > 4 * p + 3) {
                float f0 = fb[0 * N_SZ + i];
                float f1 = fb[1 * N_SZ + i];
                float f2 = fb[2 * N_SZ + i];
                float f3 = fb[3 * N_SZ + i];
                const float4* r0 = prow4 + 0 * WROW4;
                const float4* r1 = prow4 + 1 * WROW4;
                const float4* r2 = prow4 + 2 * WROW4;
                const float4* r3 = prow4 + 3 * WROW4;
                float4* wr = W4 + i * WROW4;
                #pragma unroll 4
                for (int g = p + 1; g < WROW4; g++) {
                    float4 a  = wr[g];
                    float4 q0 = r0[g], q1 = r1[g], q2 = r2[g], q3 = r3[g];
                    a.x = fmaf(-f0, q0.x, fmaf(-f1, q1.x, fmaf(-f2, q2.x, fmaf(-f3, q3.x, a.x))));
                    a.y = fmaf(-f0, q0.y, fmaf(-f1, q1.y, fmaf(-f2, q2.y, fmaf(-f3, q3.y, a.y))));
                    a.z = fmaf(-f0, q0.z, fmaf(-f1, q1.z, fmaf(-f2, q2.z, fmaf(-f3, q3.z, a.z))));
                    a.w = fmaf(-f0, q0.w, fmaf(-f1, q1.w, fmaf(-f2, q2.w, fmaf(-f3, q3.w, a.w))));
                    wr[g] = a;
                }
            }
            // copy the 4 finalized pivot rows back into W (all 256 threads)
            for (int idx = tid; idx < 4 * WROW4; idx += 256)
                W4[(4 * p + idx / WROW4) * WROW4 + (idx % WROW4)] = prow4[idx];
            __syncthreads();
        }

        // ---- back substitution (2 RHS) ----
        for (int k = N_SZ - 1; k >= 0; k--) {
            if (i < N_SZ) {
                float rinv = fast_rcp(Wf[k * WROW + k]);
                float zk0 = Wf[k * WROW + 128] * rinv;
                float zk1 = Wf[k * WROW + 129] * rinv;
                if (i < k) {
                    float a = Wf[i * WROW + k];
                    Wf[i * WROW + 128] = fmaf(-a, zk0, Wf[i * WROW + 128]);
                    Wf[i * WROW + 129] = fmaf(-a, zk1, Wf[i * WROW + 129]);
                } else if (i == k) {
                    z0s[k] = zk0;
                    z1s[k] = zk1;
                }
            }
            __syncthreads();
        }

        // ---- q_r = (I - A) z_r ----
        if (i < N_SZ) {
            float q0 = z0s[i], q1 = z1s[i];
            #pragma unroll 4
            for (int k = 0; k < N_SZ; k++) {
                float a = Bs[i * BSROW + k] - Bs[k * BSROW + i];
                q0 = fmaf(-a, z0s[k], q0);
                q1 = fmaf(-a, z1s[k], q1);
            }
            g_q0[i] = q0;
            g_q1[i] = q1;
        }
    } else {
        // ================= Leaky RNN: one thread per sequence ===============
        if (tid >= 128) return;
        const int seq = (blockIdx.x - 1) * 128 + tid;

        // fold ALPHA=0.1 into the weights
        const float W00 = 0.1f * wRec[0], W01 = 0.1f * wRec[1];
        const float W10 = 0.1f * wRec[2], W11 = 0.1f * wRec[3];
        const float I00 = 0.1f * wIn[0], I01 = 0.1f * wIn[1], I02 = 0.1f * wIn[2];
        const float I10 = 0.1f * wIn[3], I11 = 0.1f * wIn[4], I12 = 0.1f * wIn[5];

        const float4* up4 = (const float4*)(u + (size_t)seq * T_SZ * 3); // 1536 f4
        float2* hp = (float2*)g_h;

        float y0 = 0.0f, y1 = 0.0f;

        #define RNN_STEP(X0, X1, X2, TT)                                        \
            {                                                                   \
                float c0 = fmaf(I00, (X0), fmaf(I01, (X1), I02 * (X2)));        \
                float c1 = fmaf(I10, (X0), fmaf(I11, (X1), I12 * (X2)));        \
                float a0 = fmaf(0.9f, y0, c0);                                  \
                float a1 = fmaf(0.9f, y1, c1);                                  \
                float r0 = fmaxf(y0, 0.0f);                                     \
                float r1 = fmaxf(y1, 0.0f);                                     \
                float t0 = fmaf(W00, r0, a0);                                   \
                float t1 = fmaf(W10, r0, a1);                                   \
                y0 = fmaf(W01, r1, t0);                                         \
                y1 = fmaf(W11, r1, t1);                                         \
                hp[(TT) * B_SZ + seq] = make_float2(y0, y1);                    \
            }

        #define RNN_G8(b0, b1, b2, b3, b4, b5, TB)                              \
            {                                                                   \
                RNN_STEP(b0.x, b0.y, b0.z, (TB) + 0);                           \
                RNN_STEP(b0.w, b1.x, b1.y, (TB) + 1);                           \
                RNN_STEP(b1.z, b1.w, b2.x, (TB) + 2);                           \
                RNN_STEP(b2.y, b2.z, b2.w, (TB) + 3);                           \
                RNN_STEP(b3.x, b3.y, b3.z, (TB) + 4);                           \
                RNN_STEP(b3.w, b4.x, b4.y, (TB) + 5);                           \
                RNN_STEP(b4.z, b4.w, b5.x, (TB) + 6);                           \
                RNN_STEP(b5.y, b5.z, b5.w, (TB) + 7);                           \
            }

        #define LOAD6(P0, P1, P2, P3, P4, P5, GRP)                              \
            {                                                                   \
                const float4* p = up4 + (GRP) * 6;                              \
                P0 = __ldg(p + 0); P1 = __ldg(p + 1); P2 = __ldg(p + 2);        \
                P3 = __ldg(p + 3); P4 = __ldg(p + 4); P5 = __ldg(p + 5);        \
            }

        float4 A0, A1, A2, A3, A4, A5;
        float4 B0, B1, B2, B3, B4, B5;
        float4 C0, C1, C2, C3, C4, C5;

        LOAD6(A0, A1, A2, A3, A4, A5, 0);
        LOAD6(B0, B1, B2, B3, B4, B5, 1);

        #pragma unroll 1
        for (int g = 0; g < 255; g += 3) {
            LOAD6(C0, C1, C2, C3, C4, C5, g + 2);
            RNN_G8(A0, A1, A2, A3, A4, A5, (g + 0) * 8);
            LOAD6(A0, A1, A2, A3, A4, A5, g + 3);
            RNN_G8(B0, B1, B2, B3, B4, B5, (g + 1) * 8);
            if (g + 4 < 256) LOAD6(B0, B1, B2, B3, B4, B5, g + 4);
            RNN_G8(C0, C1, C2, C3, C4, C5, (g + 2) * 8);
        }
        RNN_G8(A0, A1, A2, A3, A4, A5, 255 * 8);

        #undef LOAD6
        #undef RNN_G8
        #undef RNN_STEP
    }
}

// ---------------------------------------------------------------------------
// Phase 2: out[b,t,:] = h0 * q0[:] + h1 * q1[:]
// Warp task q = b*2048 + t (t fastest) -> sequential 2KB runs per warp task.
// ---------------------------------------------------------------------------
__global__ void __launch_bounds__(256, 8) expand_kernel(float* __restrict__ out) {
    const int lane = threadIdx.x & 31;
    const int wid  = ((int)blockIdx.x * (int)blockDim.x + (int)threadIdx.x) >> 5;
    const int nw   = ((int)gridDim.x * (int)blockDim.x) >> 5;

    const float4 q0 = ((const float4*)g_q0)[lane];
    const float4 q1 = ((const float4*)g_q1)[lane];
    const float2* hp = (const float2*)g_h;
    float4* o = (float4*)out;

    const int ntask = NPAIRS / 4;   // 131072 warp-tasks of 4 timesteps
    for (int task = wid; task < ntask; task += nw) {
        int q = task << 2;          // q = b*2048 + t
        int b = q >> 11;
        int t = q & (T_SZ - 1);

        float2 h0 = hp[(t + 0) * B_SZ + b];
        float2 h1 = hp[(t + 1) * B_SZ + b];
        float2 h2 = hp[(t + 2) * B_SZ + b];
        float2 h3 = hp[(t + 3) * B_SZ + b];

        size_t base = (size_t)q * 32 + lane;
        float4 v;
        v.x = fmaf(h0.x, q0.x, h0.y * q1.x);
        v.y = fmaf(h0.x, q0.y, h0.y * q1.y);
        v.z = fmaf(h0.x, q0.z, h0.y * q1.z);
        v.w = fmaf(h0.x, q0.w, h0.y * q1.w);
        __stcs(&o[base], v);
        v.x = fmaf(h1.x, q0.x, h1.y * q1.x);
        v.y = fmaf(h1.x, q0.y, h1.y * q1.y);
        v.z = fmaf(h1.x, q0.z, h1.y * q1.z);
        v.w = fmaf(h1.x, q0.w, h1.y * q1.w);
        __stcs(&o[base + 32], v);
        v.x = fmaf(h2.x, q0.x, h2.y * q1.x);
        v.y = fmaf(h2.x, q0.y, h2.y * q1.y);
        v.z = fmaf(h2.x, q0.z, h2.y * q1.z);
        v.w = fmaf(h2.x, q0.w, h2.y * q1.w);
        __stcs(&o[base + 64], v);
        v.x = fmaf(h3.x, q0.x, h3.y * q1.x);
        v.y = fmaf(h3.x, q0.y, h3.y * q1.y);
        v.z = fmaf(h3.x, q0.z, h3.y * q1.z);
        v.w = fmaf(h3.x, q0.w, h3.y * q1.w);
        __stcs(&o[base + 96], v);
    }
}

// ---------------------------------------------------------------------------
extern "C" void kernel_launch(void* const* d_in, const int* in_sizes, int n_in,
                              void* d_out, int out_size) {
    // Identify inputs by element count:
    // u = 1572864, matB = 16384, wIn = 6, wRec = 4
    const float *u = nullptr, *matB = nullptr, *wIn = nullptr, *wRec = nullptr;
    for (int i = 0; i < n_in; i++) {
        switch (in_sizes[i]) {
            case 1572864: u    = (const float*)d_in[i]; break;
            case 16384:   matB = (const float*)d_in[i]; break;
            case 6:       wIn  = (const float*)d_in[i]; break;
            case 4:       wRec = (const float*)d_in[i]; break;
        }
    }

    // W + Bs + prow + fbuf
    const int smem = (N_SZ * WROW + N_SZ * BSROW + 4 * WROW + 4 * N_SZ)
                     * (int)sizeof(float);   // 137792 B
    cudaFuncSetAttribute(phase1_kernel,
                         cudaFuncAttributeMaxDynamicSharedMemorySize, smem);

    // block 0: solve;  blocks 1..2: RNN (128 sequences each)
    phase1_kernel<<<3, 256, smem>>>(u, matB, wIn, wRec);

    // expand: write-bandwidth bound
    expand_kernel<<<1184, 256>>>((float*)d_out);
}

// round 10
// speedup vs baseline: 1.0974x; 1.0974x over previous
#include <cuda_runtime.h>
#include <cstdint>
#include <stdint.h>

#define B_SZ   256
#define T_SZ   2048
#define N_SZ   128
#define NPAIRS (B_SZ * T_SZ)   // 524288

// Solve workspace: 128 rows x 132 floats (cols 0..127 = I+A, 128/129 = RHS)
#define WROW   132
#define WROW4  33
#define BSROW  129

// Scratch (device globals — no allocation allowed)
__device__ __align__(16) float  g_h[NPAIRS * 2];  // hidden, [t][b] float2 layout
__device__ __align__(16) float2 g_c[NPAIRS];      // input proj, [t][b] float2
__device__ __align__(16) float  g_q0[N_SZ];       // Q[:,0]
__device__ __align__(16) float  g_q1[N_SZ];       // Q[:,1]

__device__ __forceinline__ float fast_rcp(float x) {
    float r;
    asm("rcp.approx.f32 %0, %1;" : "=f"(r) : "f"(x));
    return r;
}

__device__ __forceinline__ float getc(float4 v, int m) {
    return m == 0 ? v.x : (m == 1 ? v.y : (m == 2 ? v.z : v.w));
}

// ---------------------------------------------------------------------------
// Kernel 0: input projection  c[t][b] = 0.1 * wIn @ u[b,t,:]
// Coalesced u reads (each thread: 4 consecutive timesteps = 3 float4).
// Scattered 8B writes to g_c land in L2 (4MB, L2-resident for the RNN).
// ---------------------------------------------------------------------------
__global__ void __launch_bounds__(256) proj_kernel(const float* __restrict__ u,
                                                   const float* __restrict__ wIn) {
    const float I00 = 0.1f * __ldg(wIn + 0), I01 = 0.1f * __ldg(wIn + 1),
                I02 = 0.1f * __ldg(wIn + 2);
    const float I10 = 0.1f * __ldg(wIn + 3), I11 = 0.1f * __ldg(wIn + 4),
                I12 = 0.1f * __ldg(wIn + 5);

    int p4 = (int)blockIdx.x * 256 + (int)threadIdx.x;   // 0..131071
    int b  = p4 >> 9;                 // 512 groups-of-4 per sequence
    int t0 = (p4 & 511) << 2;         // timestep base (multiple of 4)

    const float4* up = (const float4*)(u + (size_t)b * (T_SZ * 3) + (size_t)t0 * 3);
    float4 v0 = __ldg(up + 0);
    float4 v1 = __ldg(up + 1);
    float4 v2 = __ldg(up + 2);

    float2* outp = g_c + (size_t)t0 * B_SZ + b;
    outp[0]         = make_float2(fmaf(I00, v0.x, fmaf(I01, v0.y, I02 * v0.z)),
                                  fmaf(I10, v0.x, fmaf(I11, v0.y, I12 * v0.z)));
    outp[B_SZ]      = make_float2(fmaf(I00, v0.w, fmaf(I01, v1.x, I02 * v1.y)),
                                  fmaf(I10, v0.w, fmaf(I11, v1.x, I12 * v1.y)));
    outp[2 * B_SZ]  = make_float2(fmaf(I00, v1.z, fmaf(I01, v1.w, I02 * v2.x)),
                                  fmaf(I10, v1.z, fmaf(I11, v1.w, I12 * v2.x)));
    outp[3 * B_SZ]  = make_float2(fmaf(I00, v2.y, fmaf(I01, v2.z, I02 * v2.w)),
                                  fmaf(I10, v2.y, fmaf(I11, v2.z, I12 * v2.w)));
}

// ---------------------------------------------------------------------------
// Phase 1 (256 threads/block):
//   block 0:     Cayley solve — panel-4 blocked Gaussian elimination
//   blocks 1..2: leaky RNN — threads 0..127, one sequence each, reading the
//                precomputed projection g_c[t][b] (coalesced, L2-resident)
// ---------------------------------------------------------------------------
__global__ void __launch_bounds__(256) phase1_kernel(
        const float* __restrict__ matB,
        const float* __restrict__ wRec) {
    extern __shared__ float smem[];
    const int tid = threadIdx.x;

    if (blockIdx.x == 0) {
        // ================= Cayley solve: blocked GE =================
        float*  Wf    = smem;                       // [128][132]
        float4* W4    = (float4*)smem;              // row i, group g: i*33+g
        float*  Bs    = smem + N_SZ * WROW;         // [128][129]
        float*  prowf = Bs + N_SZ * BSROW;          // [4][132] corrected pivot rows
        float4* prow4 = (float4*)prowf;             // [4][33]
        float*  fb    = prowf + 4 * WROW;           // [4][128] elimination factors
        __shared__ float z0s[N_SZ], z1s[N_SZ];
        const int i = tid;                          // row (threads 0..127)

        // ---- stage matB into smem, coalesced float4 loads ----
        for (int idx = tid; idx < N_SZ * 32; idx += 256) {
            int r = idx >> 5, c4 = idx & 31;
            float4 v = ((const float4*)matB)[r * 32 + c4];
            float* dst = Bs + r * BSROW + c4 * 4;
            dst[0] = v.x; dst[1] = v.y; dst[2] = v.z; dst[3] = v.w;
        }
        __syncthreads();

        // ---- build augmented [I+A | e0 e1] ----
        if (i < N_SZ) {
            float* wr = Wf + i * WROW;
            #pragma unroll 4
            for (int j = 0; j < N_SZ; j++) {
                float a = Bs[i * BSROW + j] - Bs[j * BSROW + i];
                wr[j] = (i == j ? 1.0f : 0.0f) + a;
            }
            wr[128] = (i == 0) ? 1.0f : 0.0f;
            wr[129] = (i == 1) ? 1.0f : 0.0f;
            wr[130] = 0.0f; wr[131] = 0.0f;
        }
        __syncthreads();

        // ---- blocked forward elimination: 32 panels of 4 pivots ----
        for (int p = 0; p < 32; p++) {
            float4 cp = make_float4(0.f, 0.f, 0.f, 0.f);
            if (i < N_SZ) cp = W4[i * WROW4 + p];

            #pragma unroll
            for (int m = 0; m < 4; m++) {
                const int k = 4 * p + m;

                // corrected pivot row k -> prow[m]  (33 threads)
                if (tid < WROW4) {
                    float4 v = W4[k * WROW4 + tid];
                    #pragma unroll
                    for (int j = 0; j < 4; j++) {
                        if (j < m) {
                            float fj = fb[j * N_SZ + k];
                            float4 pr = prow4[j * WROW4 + tid];
                            v.x = fmaf(-fj, pr.x, v.x);
                            v.y = fmaf(-fj, pr.y, v.y);
                            v.z = fmaf(-fj, pr.z, v.z);
                            v.w = fmaf(-fj, pr.w, v.w);
                        }
                    }
                    prow4[m * WROW4 + tid] = v;
                }
                __syncthreads();

                // factors + register panel-slice correction
                if (i < N_SZ) {
                    float piv  = prowf[m * WROW + k];
                    float rinv = fast_rcp(piv);
                    float f = (i > k) ? getc(cp, m) * rinv : 0.0f;
                    fb[m * N_SZ + i] = f;
                    float4 pp = prow4[m * WROW4 + p];
                    if (m < 1) cp.y = fmaf(-f, pp.y, cp.y);
                    if (m < 2) cp.z = fmaf(-f, pp.z, cp.z);
                    if (m < 3) cp.w = fmaf(-f, pp.w, cp.w);
                }
                __syncthreads();
            }

            // rank-4 update of rows below the panel (one touch per row)
            if (i < N_SZ && i > 4 * p + 3) {
                float f0 = fb[0 * N_SZ + i];
                float f1 = fb[1 * N_SZ + i];
                float f2 = fb[2 * N_SZ + i];
                float f3 = fb[3 * N_SZ + i];
                const float4* r0 = prow4 + 0 * WROW4;
                const float4* r1 = prow4 + 1 * WROW4;
                const float4* r2 = prow4 + 2 * WROW4;
                const float4* r3 = prow4 + 3 * WROW4;
                float4* wr = W4 + i * WROW4;
                #pragma unroll 4
                for (int g = p + 1; g < WROW4; g++) {
                    float4 a  = wr[g];
                    float4 q0 = r0[g], q1 = r1[g], q2 = r2[g], q3 = r3[g];
                    a.x = fmaf(-f0, q0.x, fmaf(-f1, q1.x, fmaf(-f2, q2.x, fmaf(-f3, q3.x, a.x))));
                    a.y = fmaf(-f0, q0.y, fmaf(-f1, q1.y, fmaf(-f2, q2.y, fmaf(-f3, q3.y, a.y))));
                    a.z = fmaf(-f0, q0.z, fmaf(-f1, q1.z, fmaf(-f2, q2.z, fmaf(-f3, q3.z, a.z))));
                    a.w = fmaf(-f0, q0.w, fmaf(-f1, q1.w, fmaf(-f2, q2.w, fmaf(-f3, q3.w, a.w))));
                    wr[g] = a;
                }
            }
            // copy finalized pivot rows back into W
            for (int idx = tid; idx < 4 * WROW4; idx += 256)
                W4[(4 * p + idx / WROW4) * WROW4 + (idx % WROW4)] = prow4[idx];
            __syncthreads();
        }

        // ---- back substitution (2 RHS) ----
        for (int k = N_SZ - 1; k >= 0; k--) {
            if (i < N_SZ) {
                float rinv = fast_rcp(Wf[k * WROW + k]);
                float zk0 = Wf[k * WROW + 128] * rinv;
                float zk1 = Wf[k * WROW + 129] * rinv;
                if (i < k) {
                    float a = Wf[i * WROW + k];
                    Wf[i * WROW + 128] = fmaf(-a, zk0, Wf[i * WROW + 128]);
                    Wf[i * WROW + 129] = fmaf(-a, zk1, Wf[i * WROW + 129]);
                } else if (i == k) {
                    z0s[k] = zk0;
                    z1s[k] = zk1;
                }
            }
            __syncthreads();
        }

        // ---- q_r = (I - A) z_r ----
        if (i < N_SZ) {
            float q0 = z0s[i], q1 = z1s[i];
            #pragma unroll 4
            for (int k = 0; k < N_SZ; k++) {
                float a = Bs[i * BSROW + k] - Bs[k * BSROW + i];
                q0 = fmaf(-a, z0s[k], q0);
                q1 = fmaf(-a, z1s[k], q1);
            }
            g_q0[i] = q0;
            g_q1[i] = q1;
        }
    } else {
        // ====== Leaky RNN: one thread/seq, coalesced L2-resident c reads ====
        if (tid >= 128) return;
        const int seq = (blockIdx.x - 1) * 128 + tid;

        const float W00 = 0.1f * wRec[0], W01 = 0.1f * wRec[1];
        const float W10 = 0.1f * wRec[2], W11 = 0.1f * wRec[3];

        const float2* gc = g_c;
        float2* hp = (float2*)g_h;
        float y0 = 0.0f, y1 = 0.0f;

        // 12-cycle dependent chain per step; c comes precomputed
        #define RNN_STEP2(CC, TT)                                               \
            {                                                                   \
                float a0 = fmaf(0.9f, y0, CC.x);                                \
                float a1 = fmaf(0.9f, y1, CC.y);                                \
                float r0 = fmaxf(y0, 0.0f);                                     \
                float r1 = fmaxf(y1, 0.0f);                                     \
                float t0 = fmaf(W00, r0, a0);                                   \
                float t1 = fmaf(W10, r0, a1);                                   \
                y0 = fmaf(W01, r1, t0);                                         \
                y1 = fmaf(W11, r1, t1);                                         \
                hp[(TT) * B_SZ + seq] = make_float2(y0, y1);                    \
            }

        // load one 8-step group of c (coalesced float2, stride 2KB rows)
        #define LOADG(P, G)                                                     \
            {                                                                   \
                const float2* cp_ = gc + (size_t)(G) * 8 * B_SZ + seq;          \
                P##0 = __ldg(cp_ + 0 * B_SZ); P##1 = __ldg(cp_ + 1 * B_SZ);     \
                P##2 = __ldg(cp_ + 2 * B_SZ); P##3 = __ldg(cp_ + 3 * B_SZ);     \
                P##4 = __ldg(cp_ + 4 * B_SZ); P##5 = __ldg(cp_ + 5 * B_SZ);     \
                P##6 = __ldg(cp_ + 6 * B_SZ); P##7 = __ldg(cp_ + 7 * B_SZ);     \
            }

        #define RNN_G8(P, TB)                                                   \
            {                                                                   \
                RNN_STEP2(P##0, (TB) + 0); RNN_STEP2(P##1, (TB) + 1);           \
                RNN_STEP2(P##2, (TB) + 2); RNN_STEP2(P##3, (TB) + 3);           \
                RNN_STEP2(P##4, (TB) + 4); RNN_STEP2(P##5, (TB) + 5);           \
                RNN_STEP2(P##6, (TB) + 6); RNN_STEP2(P##7, (TB) + 7);           \
            }

        float2 A0, A1, A2, A3, A4, A5, A6, A7;
        float2 B0, B1, B2, B3, B4, B5, B6, B7;
        float2 C0, C1, C2, C3, C4, C5, C6, C7;

        LOADG(A, 0);
        LOADG(B, 1);

        // 256 groups of 8 steps; rotate A/B/C, loads 2-3 groups ahead
        #pragma unroll 1
        for (int g = 0; g < 255; g += 3) {
            LOADG(C, g + 2);
            RNN_G8(A, (g + 0) * 8);
            LOADG(A, g + 3);
            RNN_G8(B, (g + 1) * 8);
            if (g + 4 < 256) LOADG(B, g + 4);
            RNN_G8(C, (g + 2) * 8);
        }
        RNN_G8(A, 255 * 8);

        #undef RNN_G8
        #undef LOADG
        #undef RNN_STEP2
    }
}

// ---------------------------------------------------------------------------
// Phase 2: out[b,t,:] = h0 * q0[:] + h1 * q1[:]
// Warp task q = b*2048 + t (t fastest) -> sequential 2KB runs per warp task.
// ---------------------------------------------------------------------------
__global__ void __launch_bounds__(256, 8) expand_kernel(float* __restrict__ out) {
    const int lane = threadIdx.x & 31;
    const int wid  = ((int)blockIdx.x * (int)blockDim.x + (int)threadIdx.x) >> 5;
    const int nw   = ((int)gridDim.x * (int)blockDim.x) >> 5;

    const float4 q0 = ((const float4*)g_q0)[lane];
    const float4 q1 = ((const float4*)g_q1)[lane];
    const float2* hp = (const float2*)g_h;
    float4* o = (float4*)out;

    const int ntask = NPAIRS / 4;   // 131072 warp-tasks of 4 timesteps
    for (int task = wid; task < ntask; task += nw) {
        int q = task << 2;          // q = b*2048 + t
        int b = q >> 11;
        int t = q & (T_SZ - 1);

        float2 h0 = hp[(t + 0) * B_SZ + b];
        float2 h1 = hp[(t + 1) * B_SZ + b];
        float2 h2 = hp[(t + 2) * B_SZ + b];
        float2 h3 = hp[(t + 3) * B_SZ + b];

        size_t base = (size_t)q * 32 + lane;
        float4 v;
        v.x = fmaf(h0.x, q0.x, h0.y * q1.x);
        v.y = fmaf(h0.x, q0.y, h0.y * q1.y);
        v.z = fmaf(h0.x, q0.z, h0.y * q1.z);
        v.w = fmaf(h0.x, q0.w, h0.y * q1.w);
        __stcs(&o[base], v);
        v.x = fmaf(h1.x, q0.x, h1.y * q1.x);
        v.y = fmaf(h1.x, q0.y, h1.y * q1.y);
        v.z = fmaf(h1.x, q0.z, h1.y * q1.z);
        v.w = fmaf(h1.x, q0.w, h1.y * q1.w);
        __stcs(&o[base + 32], v);
        v.x = fmaf(h2.x, q0.x, h2.y * q1.x);
        v.y = fmaf(h2.x, q0.y, h2.y * q1.y);
        v.z = fmaf(h2.x, q0.z, h2.y * q1.z);
        v.w = fmaf(h2.x, q0.w, h2.y * q1.w);
        __stcs(&o[base + 64], v);
        v.x = fmaf(h3.x, q0.x, h3.y * q1.x);
        v.y = fmaf(h3.x, q0.y, h3.y * q1.y);
        v.z = fmaf(h3.x, q0.z, h3.y * q1.z);
        v.w = fmaf(h3.x, q0.w, h3.y * q1.w);
        __stcs(&o[base + 96], v);
    }
}

// ---------------------------------------------------------------------------
extern "C" void kernel_launch(void* const* d_in, const int* in_sizes, int n_in,
                              void* d_out, int out_size) {
    // Identify inputs by element count:
    // u = 1572864, matB = 16384, wIn = 6, wRec = 4
    const float *u = nullptr, *matB = nullptr, *wIn = nullptr, *wRec = nullptr;
    for (int i = 0; i < n_in; i++) {
        switch (in_sizes[i]) {
            case 1572864: u    = (const float*)d_in[i]; break;
            case 16384:   matB = (const float*)d_in[i]; break;
            case 6:       wIn  = (const float*)d_in[i]; break;
            case 4:       wRec = (const float*)d_in[i]; break;
        }
    }

    const int smem = (N_SZ * WROW + N_SZ * BSROW + 4 * WROW + 4 * N_SZ)
                     * (int)sizeof(float);   // 137792 B
    cudaFuncSetAttribute(phase1_kernel,
                         cudaFuncAttributeMaxDynamicSharedMemorySize, smem);

    // 0) input projection: u -> g_c  (coalesced reads, ~3us)
    proj_kernel<<<512, 256>>>(u, wIn);

    // 1) block 0: solve;  blocks 1..2: RNN (reads g_c from L2)
    phase1_kernel<<<3, 256, smem>>>(matB, wRec);

    // 2) expand: write-bandwidth bound
    expand_kernel<<<1184, 256>>>((float*)d_out);
}

// round 11
// speedup vs baseline: 1.4683x; 1.3381x over previous
#include <cuda_runtime.h>
#include <cstdint>
#include <stdint.h>

#define B_SZ   256
#define T_SZ   2048
#define N_SZ   128
#define NPAIRS (B_SZ * T_SZ)   // 524288

// Solve workspace: 128 rows x 132 floats (cols 0..127 = I+A, 128/129 = RHS)
#define WROW   132
#define WROW4  33
#define BSROW  129

#define RNN_BLOCKS 8
#define SEQ_PB     32          // sequences (threads) per RNN block = 1 warp

// Scratch (device globals — no allocation allowed)
__device__ __align__(16) float  g_h[NPAIRS * 2];  // hidden, [t][b] float2 layout
__device__ __align__(16) float2 g_c[NPAIRS];      // input proj, [t][b] float2
__device__ __align__(16) float  g_q0[N_SZ];       // Q[:,0]
__device__ __align__(16) float  g_q1[N_SZ];       // Q[:,1]

__device__ __forceinline__ float fast_rcp(float x) {
    float r;
    asm("rcp.approx.f32 %0, %1;" : "=f"(r) : "f"(x));
    return r;
}

__device__ __forceinline__ float getc(float4 v, int m) {
    return m == 0 ? v.x : (m == 1 ? v.y : (m == 2 ? v.z : v.w));
}

// ---------------------------------------------------------------------------
// Kernel 0: input projection  c[t][b] = 0.1 * wIn @ u[b,t,:]
// ---------------------------------------------------------------------------
__global__ void __launch_bounds__(256) proj_kernel(const float* __restrict__ u,
                                                   const float* __restrict__ wIn) {
    const float I00 = 0.1f * __ldg(wIn + 0), I01 = 0.1f * __ldg(wIn + 1),
                I02 = 0.1f * __ldg(wIn + 2);
    const float I10 = 0.1f * __ldg(wIn + 3), I11 = 0.1f * __ldg(wIn + 4),
                I12 = 0.1f * __ldg(wIn + 5);

    int p4 = (int)blockIdx.x * 256 + (int)threadIdx.x;   // 0..131071
    int b  = p4 >> 9;                 // 512 groups-of-4 per sequence
    int t0 = (p4 & 511) << 2;         // timestep base (multiple of 4)

    const float4* up = (const float4*)(u + (size_t)b * (T_SZ * 3) + (size_t)t0 * 3);
    float4 v0 = __ldg(up + 0);
    float4 v1 = __ldg(up + 1);
    float4 v2 = __ldg(up + 2);

    float2* outp = g_c + (size_t)t0 * B_SZ + b;
    outp[0]         = make_float2(fmaf(I00, v0.x, fmaf(I01, v0.y, I02 * v0.z)),
                                  fmaf(I10, v0.x, fmaf(I11, v0.y, I12 * v0.z)));
    outp[B_SZ]      = make_float2(fmaf(I00, v0.w, fmaf(I01, v1.x, I02 * v1.y)),
                                  fmaf(I10, v0.w, fmaf(I11, v1.x, I12 * v1.y)));
    outp[2 * B_SZ]  = make_float2(fmaf(I00, v1.z, fmaf(I01, v1.w, I02 * v2.x)),
                                  fmaf(I10, v1.z, fmaf(I11, v1.w, I12 * v2.x)));
    outp[3 * B_SZ]  = make_float2(fmaf(I00, v2.y, fmaf(I01, v2.z, I02 * v2.w)),
                                  fmaf(I10, v2.y, fmaf(I11, v2.z, I12 * v2.w)));
}

// ---------------------------------------------------------------------------
// Phase 1:
//   block 0:     Cayley solve — panel-4 blocked Gaussian elimination (256 thr)
//   blocks 1..8: leaky RNN — ONE WARP each, 32 sequences per block,
//                4-buffer rotation reading g_c (coalesced, L2-resident)
// ---------------------------------------------------------------------------
__global__ void __launch_bounds__(256) phase1_kernel(
        const float* __restrict__ matB,
        const float* __restrict__ wRec) {
    extern __shared__ float smem[];
    const int tid = threadIdx.x;

    if (blockIdx.x == 0) {
        // ================= Cayley solve: blocked GE =================
        float*  Wf    = smem;                       // [128][132]
        float4* W4    = (float4*)smem;              // row i, group g: i*33+g
        float*  Bs    = smem + N_SZ * WROW;         // [128][129]
        float*  prowf = Bs + N_SZ * BSROW;          // [4][132] corrected pivot rows
        float4* prow4 = (float4*)prowf;             // [4][33]
        float*  fb    = prowf + 4 * WROW;           // [4][128] elimination factors
        __shared__ float z0s[N_SZ], z1s[N_SZ];
        const int i = tid;                          // row (threads 0..127)

        // ---- stage matB into smem, coalesced float4 loads ----
        for (int idx = tid; idx < N_SZ * 32; idx += 256) {
            int r = idx >> 5, c4 = idx & 31;
            float4 v = ((const float4*)matB)[r * 32 + c4];
            float* dst = Bs + r * BSROW + c4 * 4;
            dst[0] = v.x; dst[1] = v.y; dst[2] = v.z; dst[3] = v.w;
        }
        __syncthreads();

        // ---- build augmented [I+A | e0 e1] ----
        if (i < N_SZ) {
            float* wr = Wf + i * WROW;
            #pragma unroll 4
            for (int j = 0; j < N_SZ; j++) {
                float a = Bs[i * BSROW + j] - Bs[j * BSROW + i];
                wr[j] = (i == j ? 1.0f : 0.0f) + a;
            }
            wr[128] = (i == 0) ? 1.0f : 0.0f;
            wr[129] = (i == 1) ? 1.0f : 0.0f;
            wr[130] = 0.0f; wr[131] = 0.0f;
        }
        __syncthreads();

        // ---- blocked forward elimination: 32 panels of 4 pivots ----
        for (int p = 0; p < 32; p++) {
            float4 cp = make_float4(0.f, 0.f, 0.f, 0.f);
            if (i < N_SZ) cp = W4[i * WROW4 + p];

            #pragma unroll
            for (int m = 0; m < 4; m++) {
                const int k = 4 * p + m;

                // corrected pivot row k -> prow[m]  (33 threads)
                if (tid < WROW4) {
                    float4 v = W4[k * WROW4 + tid];
                    #pragma unroll
                    for (int j = 0; j < 4; j++) {
                        if (j < m) {
                            float fj = fb[j * N_SZ + k];
                            float4 pr = prow4[j * WROW4 + tid];
                            v.x = fmaf(-fj, pr.x, v.x);
                            v.y = fmaf(-fj, pr.y, v.y);
                            v.z = fmaf(-fj, pr.z, v.z);
                            v.w = fmaf(-fj, pr.w, v.w);
                        }
                    }
                    prow4[m * WROW4 + tid] = v;
                }
                __syncthreads();

                // factors + register panel-slice correction
                if (i < N_SZ) {
                    float piv  = prowf[m * WROW + k];
                    float rinv = fast_rcp(piv);
                    float f = (i > k) ? getc(cp, m) * rinv : 0.0f;
                    fb[m * N_SZ + i] = f;
                    float4 pp = prow4[m * WROW4 + p];
                    if (m < 1) cp.y = fmaf(-f, pp.y, cp.y);
                    if (m < 2) cp.z = fmaf(-f, pp.z, cp.z);
                    if (m < 3) cp.w = fmaf(-f, pp.w, cp.w);
                }
                __syncthreads();
            }

            // rank-4 update of rows below the panel (one touch per row)
            if (i < N_SZ && i > 4 * p + 3) {
                float f0 = fb[0 * N_SZ + i];
                float f1 = fb[1 * N_SZ + i];
                float f2 = fb[2 * N_SZ + i];
                float f3 = fb[3 * N_SZ + i];
                const float4* r0 = prow4 + 0 * WROW4;
                const float4* r1 = prow4 + 1 * WROW4;
                const float4* r2 = prow4 + 2 * WROW4;
                const float4* r3 = prow4 + 3 * WROW4;
                float4* wr = W4 + i * WROW4;
                #pragma unroll 4
                for (int g = p + 1; g < WROW4; g++) {
                    float4 a  = wr[g];
                    float4 q0 = r0[g], q1 = r1[g], q2 = r2[g], q3 = r3[g];
                    a.x = fmaf(-f0, q0.x, fmaf(-f1, q1.x, fmaf(-f2, q2.x, fmaf(-f3, q3.x, a.x))));
                    a.y = fmaf(-f0, q0.y, fmaf(-f1, q1.y, fmaf(-f2, q2.y, fmaf(-f3, q3.y, a.y))));
                    a.z = fmaf(-f0, q0.z, fmaf(-f1, q1.z, fmaf(-f2, q2.z, fmaf(-f3, q3.z, a.z))));
                    a.w = fmaf(-f0, q0.w, fmaf(-f1, q1.w, fmaf(-f2, q2.w, fmaf(-f3, q3.w, a.w))));
                    wr[g] = a;
                }
            }
            // copy finalized pivot rows back into W
            for (int idx = tid; idx < 4 * WROW4; idx += 256)
                W4[(4 * p + idx / WROW4) * WROW4 + (idx % WROW4)] = prow4[idx];
            __syncthreads();
        }

        // ---- back substitution (2 RHS) ----
        for (int k = N_SZ - 1; k >= 0; k--) {
            if (i < N_SZ) {
                float rinv = fast_rcp(Wf[k * WROW + k]);
                float zk0 = Wf[k * WROW + 128] * rinv;
                float zk1 = Wf[k * WROW + 129] * rinv;
                if (i < k) {
                    float a = Wf[i * WROW + k];
                    Wf[i * WROW + 128] = fmaf(-a, zk0, Wf[i * WROW + 128]);
                    Wf[i * WROW + 129] = fmaf(-a, zk1, Wf[i * WROW + 129]);
                } else if (i == k) {
                    z0s[k] = zk0;
                    z1s[k] = zk1;
                }
            }
            __syncthreads();
        }

        // ---- q_r = (I - A) z_r ----
        if (i < N_SZ) {
            float q0 = z0s[i], q1 = z1s[i];
            #pragma unroll 4
            for (int k = 0; k < N_SZ; k++) {
                float a = Bs[i * BSROW + k] - Bs[k * BSROW + i];
                q0 = fmaf(-a, z0s[k], q0);
                q1 = fmaf(-a, z1s[k], q1);
            }
            g_q0[i] = q0;
            g_q1[i] = q1;
        }
    } else {
        // ====== Leaky RNN: ONE WARP per block, 32 sequences ======
        if (tid >= SEQ_PB) return;
        const int seq = (blockIdx.x - 1) * SEQ_PB + tid;

        const float W00 = 0.1f * wRec[0], W01 = 0.1f * wRec[1];
        const float W10 = 0.1f * wRec[2], W11 = 0.1f * wRec[3];

        const float2* gc = g_c;
        float2* hp = (float2*)g_h;
        float y0 = 0.0f, y1 = 0.0f;

        #define RNN_STEP2(CC, TT)                                               \
            {                                                                   \
                float a0 = fmaf(0.9f, y0, CC.x);                                \
                float a1 = fmaf(0.9f, y1, CC.y);                                \
                float r0 = fmaxf(y0, 0.0f);                                     \
                float r1 = fmaxf(y1, 0.0f);                                     \
                float t0 = fmaf(W00, r0, a0);                                   \
                float t1 = fmaf(W10, r0, a1);                                   \
                y0 = fmaf(W01, r1, t0);                                         \
                y1 = fmaf(W11, r1, t1);                                         \
                hp[(TT) * B_SZ + seq] = make_float2(y0, y1);                    \
            }

        #define LOADG(P, G)                                                     \
            {                                                                   \
                const float2* cp_ = gc + (size_t)(G) * 8 * B_SZ + seq;          \
                P##0 = __ldg(cp_ + 0 * B_SZ); P##1 = __ldg(cp_ + 1 * B_SZ);     \
                P##2 = __ldg(cp_ + 2 * B_SZ); P##3 = __ldg(cp_ + 3 * B_SZ);     \
                P##4 = __ldg(cp_ + 4 * B_SZ); P##5 = __ldg(cp_ + 5 * B_SZ);     \
                P##6 = __ldg(cp_ + 6 * B_SZ); P##7 = __ldg(cp_ + 7 * B_SZ);     \
            }

        #define RNN_G8(P, TB)                                                   \
            {                                                                   \
                RNN_STEP2(P##0, (TB) + 0); RNN_STEP2(P##1, (TB) + 1);           \
                RNN_STEP2(P##2, (TB) + 2); RNN_STEP2(P##3, (TB) + 3);           \
                RNN_STEP2(P##4, (TB) + 4); RNN_STEP2(P##5, (TB) + 5);           \
                RNN_STEP2(P##6, (TB) + 6); RNN_STEP2(P##7, (TB) + 7);           \
            }

        float2 A0, A1, A2, A3, A4, A5, A6, A7;
        float2 B0, B1, B2, B3, B4, B5, B6, B7;
        float2 C0, C1, C2, C3, C4, C5, C6, C7;
        float2 D0, D1, D2, D3, D4, D5, D6, D7;

        LOADG(A, 0);
        LOADG(B, 1);
        LOADG(C, 2);

        // 256 groups of 8 steps; 4-buffer rotation, loads 3-4 groups ahead
        #pragma unroll 1
        for (int g = 0; g < 252; g += 4) {
            LOADG(D, g + 3);
            RNN_G8(A, (g + 0) * 8);
            LOADG(A, g + 4);
            RNN_G8(B, (g + 1) * 8);
            LOADG(B, g + 5);
            RNN_G8(C, (g + 2) * 8);
            LOADG(C, g + 6);
            RNN_G8(D, (g + 3) * 8);
        }
        // tail: groups 252..255 (A,B,C already loaded; D = 255)
        LOADG(D, 255);
        RNN_G8(A, 252 * 8);
        RNN_G8(B, 253 * 8);
        RNN_G8(C, 254 * 8);
        RNN_G8(D, 255 * 8);

        #undef RNN_G8
        #undef LOADG
        #undef RNN_STEP2
    }
}

// ---------------------------------------------------------------------------
// Phase 2: out[b,t,:] = h0 * q0[:] + h1 * q1[:]
// ---------------------------------------------------------------------------
__global__ void __launch_bounds__(256, 8) expand_kernel(float* __restrict__ out) {
    const int lane = threadIdx.x & 31;
    const int wid  = ((int)blockIdx.x * (int)blockDim.x + (int)threadIdx.x) >> 5;
    const int nw   = ((int)gridDim.x * (int)blockDim.x) >> 5;

    const float4 q0 = ((const float4*)g_q0)[lane];
    const float4 q1 = ((const float4*)g_q1)[lane];
    const float2* hp = (const float2*)g_h;
    float4* o = (float4*)out;

    const int ntask = NPAIRS / 4;   // 131072 warp-tasks of 4 timesteps
    for (int task = wid; task < ntask; task += nw) {
        int q = task << 2;          // q = b*2048 + t
        int b = q >> 11;
        int t = q & (T_SZ - 1);

        float2 h0 = hp[(t + 0) * B_SZ + b];
        float2 h1 = hp[(t + 1) * B_SZ + b];
        float2 h2 = hp[(t + 2) * B_SZ + b];
        float2 h3 = hp[(t + 3) * B_SZ + b];

        size_t base = (size_t)q * 32 + lane;
        float4 v;
        v.x = fmaf(h0.x, q0.x, h0.y * q1.x);
        v.y = fmaf(h0.x, q0.y, h0.y * q1.y);
        v.z = fmaf(h0.x, q0.z, h0.y * q1.z);
        v.w = fmaf(h0.x, q0.w, h0.y * q1.w);
        __stcs(&o[base], v);
        v.x = fmaf(h1.x, q0.x, h1.y * q1.x);
        v.y = fmaf(h1.x, q0.y, h1.y * q1.y);
        v.z = fmaf(h1.x, q0.z, h1.y * q1.z);
        v.w = fmaf(h1.x, q0.w, h1.y * q1.w);
        __stcs(&o[base + 32], v);
        v.x = fmaf(h2.x, q0.x, h2.y * q1.x);
        v.y = fmaf(h2.x, q0.y, h2.y * q1.y);
        v.z = fmaf(h2.x, q0.z, h2.y * q1.z);
        v.w = fmaf(h2.x, q0.w, h2.y * q1.w);
        __stcs(&o[base + 64], v);
        v.x = fmaf(h3.x, q0.x, h3.y * q1.x);
        v.y = fmaf(h3.x, q0.y, h3.y * q1.y);
        v.z = fmaf(h3.x, q0.z, h3.y * q1.z);
        v.w = fmaf(h3.x, q0.w, h3.y * q1.w);
        __stcs(&o[base + 96], v);
    }
}

// ---------------------------------------------------------------------------
extern "C" void kernel_launch(void* const* d_in, const int* in_sizes, int n_in,
                              void* d_out, int out_size) {
    // Identify inputs by element count:
    // u = 1572864, matB = 16384, wIn = 6, wRec = 4
    const float *u = nullptr, *matB = nullptr, *wIn = nullptr, *wRec = nullptr;
    for (int i = 0; i < n_in; i++) {
        switch (in_sizes[i]) {
            case 1572864: u    = (const float*)d_in[i]; break;
            case 16384:   matB = (const float*)d_in[i]; break;
            case 6:       wIn  = (const float*)d_in[i]; break;
            case 4:       wRec = (const float*)d_in[i]; break;
        }
    }

    const int smem = (N_SZ * WROW + N_SZ * BSROW + 4 * WROW + 4 * N_SZ)
                     * (int)sizeof(float);   // 137792 B
    cudaFuncSetAttribute(phase1_kernel,
                         cudaFuncAttributeMaxDynamicSharedMemorySize, smem);

    // 0) input projection: u -> g_c  (coalesced reads)
    proj_kernel<<<512, 256>>>(u, wIn);

    // 1) block 0: solve;  blocks 1..8: RNN (1 warp each, 32 seqs)
    phase1_kernel<<<1 + RNN_BLOCKS, 256, smem>>>(matB, wRec);

    // 2) expand: write-bandwidth bound
    expand_kernel<<<1184, 256>>>((float*)d_out);
}